// round 2
// baseline (speedup 1.0000x reference)
#include <cuda_runtime.h>
#include <cuda_bf16.h>
#include <math.h>

// Problem constants
#define H    2048
#define E    8
#define I16  16
#define NTOK 8192          // B*T = 2*4096
#define NB   64            // bucket ids lo*8+hi (28 valid)
#define TB   64            // tokens per tile in expert kernel
#define HCA  512           // h-chunk for down phase
#define HCB  256           // h-chunk for up phase
#define DSP  516           // Ds row pitch (floats), 16B-aligned, bank-stride 4
#define USP  260           // Us row pitch (floats)

// ---------------- device scratch (static, no allocations) ----------------
__device__ int    g_count[NB];
__device__ int    g_tok[NB][NTOK];
__device__ float2 g_gate[NB][NTOK];   // (gate_lo, gate_hi)

// ---------------- K0: zero bucket counts ----------------
__global__ void zero_counts_kernel() {
    if (threadIdx.x < NB) g_count[threadIdx.x] = 0;
}

// ---------------- K1: router + bucket scatter ----------------
// 256 threads = 8 warps; each warp handles one token. Grid = NTOK/8.
__global__ void router_kernel(const float* __restrict__ x,
                              const float* __restrict__ rw) {
    extern __shared__ float Rs[];   // [E][H] = 64 KB
    for (int idx = threadIdx.x; idx < (E * H) / 4; idx += blockDim.x)
        ((float4*)Rs)[idx] = ((const float4*)rw)[idx];
    __syncthreads();

    const int w = threadIdx.x >> 5;
    const int l = threadIdx.x & 31;
    const int t = blockIdx.x * 8 + w;

    const float4* xr = (const float4*)(x + (size_t)t * H);
    float4 acc[E];
#pragma unroll
    for (int e = 0; e < E; e++) acc[e] = make_float4(0.f, 0.f, 0.f, 0.f);

#pragma unroll 4
    for (int s = 0; s < 16; s++) {
        float4 xv = xr[l + 32 * s];
#pragma unroll
        for (int e = 0; e < E; e++) {
            float4 wv = ((const float4*)(Rs + e * H))[l + 32 * s];
            acc[e].x = fmaf(xv.x, wv.x, acc[e].x);
            acc[e].y = fmaf(xv.y, wv.y, acc[e].y);
            acc[e].z = fmaf(xv.z, wv.z, acc[e].z);
            acc[e].w = fmaf(xv.w, wv.w, acc[e].w);
        }
    }

    float lg[E];
#pragma unroll
    for (int e = 0; e < E; e++) {
        float v = (acc[e].x + acc[e].y) + (acc[e].z + acc[e].w);
#pragma unroll
        for (int o = 16; o > 0; o >>= 1) v += __shfl_xor_sync(0xffffffffu, v, o);
        lg[e] = v;
    }

    if (l == 0) {
        float m = lg[0];
#pragma unroll
        for (int e = 1; e < E; e++) m = fmaxf(m, lg[e]);
        float wgt[E]; float ssum = 0.f;
#pragma unroll
        for (int e = 0; e < E; e++) { wgt[e] = __expf(lg[e] - m); ssum += wgt[e]; }
        float inv = 1.f / ssum;

        int i1 = 0; float v1 = wgt[0];
#pragma unroll
        for (int e = 1; e < E; e++) if (wgt[e] > v1) { v1 = wgt[e]; i1 = e; }
        int i2 = -1; float v2 = -1.f;
#pragma unroll
        for (int e = 0; e < E; e++)
            if (e != i1 && wgt[e] > v2) { v2 = wgt[e]; i2 = e; }

        float g1 = v1 * inv, g2 = v2 * inv;
        int lo, hi; float glo, ghi;
        if (i1 < i2) { lo = i1; hi = i2; glo = g1; ghi = g2; }
        else         { lo = i2; hi = i1; glo = g2; ghi = g1; }
        int p = lo * 8 + hi;
        int slot = atomicAdd(&g_count[p], 1);
        g_tok[p][slot]  = t;
        g_gate[p][slot] = make_float2(glo, ghi);
    }
}

// ---------------- K2: expert compute per bucket tile ----------------
// grid = (16, 64); 256 threads = 8 warps. Tile = TB tokens of bucket p.
// Phase A (down): lane <-> intermediate i (0..31 = [e_lo 16, e_hi 16]),
//                 warp <-> token, acc carried across 4 h-chunks. No reduction.
// Phase B (up):   warp <-> token, lane <-> 4-wide h slice; A broadcast via smem.
__global__ void expert_kernel(const float* __restrict__ x,
                              const float* __restrict__ dw,
                              const float* __restrict__ uw,
                              float* __restrict__ out) {
    const int p  = blockIdx.y;
    const int lo = p >> 3, hi = p & 7;
    if (lo >= hi) return;                 // block-uniform: safe
    const int cnt = g_count[p];
    if (cnt == 0) return;

    extern __shared__ float sm[];
    float* Ds = sm;                        // [32][DSP]  (phase A)
    float* Us = sm;                        // [32][USP]  (phase B, reuses Ds)
    float* Xs = sm + 32 * DSP;             // [8][HCA]
    float* As = sm + 32 * DSP + 8 * HCA;   // [TB][32]

    const int w = threadIdx.x >> 5;
    const int l = threadIdx.x & 31;

    for (int tile = blockIdx.x; tile * TB < cnt; tile += gridDim.x) {
        const int base = tile * TB;
        const int n = min(TB, cnt - base);

        // ---------------- Phase A: a'[t][i] ----------------
        float4 acc[8];
#pragma unroll
        for (int k = 0; k < 8; k++) acc[k] = make_float4(0.f, 0.f, 0.f, 0.f);

        for (int c = 0; c < 4; c++) {
            __syncthreads();   // Ds/Us region free from prior phase
            // stage Ds[32][HCA]: rows 0..15 = expert lo, 16..31 = expert hi
            for (int idx = threadIdx.x; idx < 32 * (HCA / 4); idx += 256) {
                int r = idx >> 7;            // 0..31
                int q = idx & 127;           // float4 index within row
                int e = (r < 16) ? lo : hi;
                const float4* src = (const float4*)(dw + ((size_t)(e * I16 + (r & 15))) * H + c * HCA);
                *(float4*)(Ds + r * DSP + 4 * q) = src[q];
            }
            __syncthreads();

#pragma unroll
            for (int k = 0; k < 8; k++) {
                int tl = k * 8 + w;          // warp-uniform
                if (tl >= n) continue;
                int tg = g_tok[p][base + tl];
                // stage this token's x chunk into the warp's smem strip
                const float4* xr = (const float4*)(x + (size_t)tg * H + c * HCA);
                float4* xs = (float4*)(Xs + w * HCA);
                xs[l] = xr[l]; xs[l + 32] = xr[l + 32];
                xs[l + 64] = xr[l + 64]; xs[l + 96] = xr[l + 96];
                __syncwarp();

                const float4* Xv = (const float4*)(Xs + w * HCA);
                const float4* Dv = (const float4*)(Ds + l * DSP);
                float4 a = acc[k];
#pragma unroll 4
                for (int s = 0; s < HCA / 4; s++) {
                    float4 xv = Xv[s];       // broadcast
                    float4 dv = Dv[s];       // conflict-free (bank stride 4)
                    a.x = fmaf(xv.x, dv.x, a.x);
                    a.y = fmaf(xv.y, dv.y, a.y);
                    a.z = fmaf(xv.z, dv.z, a.z);
                    a.w = fmaf(xv.w, dv.w, a.w);
                }
                acc[k] = a;
                __syncwarp();
            }
        }

        // finalize: silu + gate, store to As
#pragma unroll
        for (int k = 0; k < 8; k++) {
            int tl = k * 8 + w;
            if (tl >= n) continue;
            float2 g = g_gate[p][base + tl];
            float hv = (acc[k].x + acc[k].y) + (acc[k].z + acc[k].w);
            float sig = 1.f / (1.f + __expf(-hv));
            float gate = (l < 16) ? g.x : g.y;
            As[tl * 32 + l] = gate * hv * sig;
        }
        __syncthreads();

        // ---------------- Phase B: out[t][h] = sum_i A[t][i] * U[i][h] -------
        for (int hc = 0; hc < H; hc += HCB) {
            // stage Us[32][HCB]: Us[i][h] = up_w[e(i)][hc+h][i&15]
            for (int idx = threadIdx.x; idx < 2 * HCB * 4; idx += 256) {
                int e  = idx >> 10;          // 0 -> lo, 1 -> hi
                int rm = idx & 1023;
                int h  = rm >> 2;
                int iq = rm & 3;
                int eg = e ? hi : lo;
                float4 v = *(const float4*)(uw + ((size_t)eg * H + hc + h) * I16 + 4 * iq);
                int rb = e * 16 + 4 * iq;
                Us[(rb + 0) * USP + h] = v.x;
                Us[(rb + 1) * USP + h] = v.y;
                Us[(rb + 2) * USP + h] = v.z;
                Us[(rb + 3) * USP + h] = v.w;
            }
            __syncthreads();

#pragma unroll
            for (int k = 0; k < 8; k++) {
                int tl = k * 8 + w;
                if (tl >= n) continue;
                const float* arow = As + tl * 32;
                float4 a0 = make_float4(0.f, 0.f, 0.f, 0.f);
                float4 a1 = make_float4(0.f, 0.f, 0.f, 0.f);
#pragma unroll
                for (int i = 0; i < 32; i++) {
                    float av  = arow[i];     // LDS broadcast
                    float4 u0 = *(const float4*)(Us + i * USP + 4 * l);
                    float4 u1 = *(const float4*)(Us + i * USP + 128 + 4 * l);
                    a0.x = fmaf(av, u0.x, a0.x);
                    a0.y = fmaf(av, u0.y, a0.y);
                    a0.z = fmaf(av, u0.z, a0.z);
                    a0.w = fmaf(av, u0.w, a0.w);
                    a1.x = fmaf(av, u1.x, a1.x);
                    a1.y = fmaf(av, u1.y, a1.y);
                    a1.z = fmaf(av, u1.z, a1.z);
                    a1.w = fmaf(av, u1.w, a1.w);
                }
                int tg = g_tok[p][base + tl];
                float4* o = (float4*)(out + (size_t)tg * H + hc);
                o[l]      = a0;
                o[l + 32] = a1;
            }
            __syncthreads();
        }
    }
}

// ---------------- launch ----------------
extern "C" void kernel_launch(void* const* d_in, const int* in_sizes, int n_in,
                              void* d_out, int out_size) {
    const float* x  = (const float*)d_in[0];
    const float* rw = (const float*)d_in[1];
    const float* dw = (const float*)d_in[2];
    const float* uw = (const float*)d_in[3];
    float* out = (float*)d_out;

    const int rs_smem = E * H * sizeof(float);                       // 64 KB
    const int ek_smem = (32 * DSP + 8 * HCA + TB * 32) * sizeof(float); // ~90.6 KB
    cudaFuncSetAttribute(router_kernel, cudaFuncAttributeMaxDynamicSharedMemorySize, rs_smem);
    cudaFuncSetAttribute(expert_kernel, cudaFuncAttributeMaxDynamicSharedMemorySize, ek_smem);

    zero_counts_kernel<<<1, 64>>>();
    router_kernel<<<NTOK / 8, 256, rs_smem>>>(x, rw);
    expert_kernel<<<dim3(16, NB), 256, ek_smem>>>(x, dw, uw, out);
}

// round 3
// speedup vs baseline: 2.6081x; 2.6081x over previous
#include <cuda_runtime.h>
#include <cuda_bf16.h>
#include <math.h>

// Problem constants
#define H    2048
#define E    8
#define I16  16
#define NTOK 8192          // B*T = 2*4096
#define NB   64            // bucket ids lo*8+hi (28 valid)
#define TB   64            // tokens per tile
#define KC   256           // k-chunk (phase A)
#define XP   260           // Xs/Ds row pitch (floats): 260 mod 32 = 4 -> bank stride 4
#define UP   260           // Us row pitch (floats)
#define ASP  33            // As row pitch (floats)

// smem layout (float offsets)
#define XS_OFF  0                      // Xs[64][XP]
#define DS_OFF  (64 * XP)              // Ds[32][XP]   = 16640
#define RED_OFF (DS_OFF + 32 * XP)     // Red[4][2048] = 24960
#define AS_OFF  (RED_OFF + 4 * 2048)   // As[64][ASP]  = 33152
#define SM_FLOATS (AS_OFF + 64 * ASP)  // 35264 floats = 141056 B

// ---------------- device scratch (static, no allocations) ----------------
__device__ int    g_count[NB];
__device__ int    g_tok[NB][NTOK];
__device__ float2 g_gate[NB][NTOK];   // (gate_lo, gate_hi)

// ---------------- K0: zero bucket counts ----------------
__global__ void zero_counts_kernel() {
    if (threadIdx.x < NB) g_count[threadIdx.x] = 0;
}

// ---------------- K1: router + bucket scatter ----------------
__global__ void router_kernel(const float* __restrict__ x,
                              const float* __restrict__ rw) {
    extern __shared__ float Rs[];   // [E][H] = 64 KB
    for (int idx = threadIdx.x; idx < (E * H) / 4; idx += blockDim.x)
        ((float4*)Rs)[idx] = ((const float4*)rw)[idx];
    __syncthreads();

    const int w = threadIdx.x >> 5;
    const int l = threadIdx.x & 31;
    const int t = blockIdx.x * 8 + w;

    const float4* xr = (const float4*)(x + (size_t)t * H);
    float4 acc[E];
#pragma unroll
    for (int e = 0; e < E; e++) acc[e] = make_float4(0.f, 0.f, 0.f, 0.f);

#pragma unroll 4
    for (int s = 0; s < 16; s++) {
        float4 xv = xr[l + 32 * s];
#pragma unroll
        for (int e = 0; e < E; e++) {
            float4 wv = ((const float4*)(Rs + e * H))[l + 32 * s];
            acc[e].x = fmaf(xv.x, wv.x, acc[e].x);
            acc[e].y = fmaf(xv.y, wv.y, acc[e].y);
            acc[e].z = fmaf(xv.z, wv.z, acc[e].z);
            acc[e].w = fmaf(xv.w, wv.w, acc[e].w);
        }
    }

    float lg[E];
#pragma unroll
    for (int e = 0; e < E; e++) {
        float v = (acc[e].x + acc[e].y) + (acc[e].z + acc[e].w);
#pragma unroll
        for (int o = 16; o > 0; o >>= 1) v += __shfl_xor_sync(0xffffffffu, v, o);
        lg[e] = v;
    }

    if (l == 0) {
        float m = lg[0];
#pragma unroll
        for (int e = 1; e < E; e++) m = fmaxf(m, lg[e]);
        float wgt[E]; float ssum = 0.f;
#pragma unroll
        for (int e = 0; e < E; e++) { wgt[e] = __expf(lg[e] - m); ssum += wgt[e]; }
        float inv = 1.f / ssum;

        int i1 = 0; float v1 = wgt[0];
#pragma unroll
        for (int e = 1; e < E; e++) if (wgt[e] > v1) { v1 = wgt[e]; i1 = e; }
        int i2 = -1; float v2 = -1.f;
#pragma unroll
        for (int e = 0; e < E; e++)
            if (e != i1 && wgt[e] > v2) { v2 = wgt[e]; i2 = e; }

        float g1 = v1 * inv, g2 = v2 * inv;
        int lo, hi; float glo, ghi;
        if (i1 < i2) { lo = i1; hi = i2; glo = g1; ghi = g2; }
        else         { lo = i2; hi = i1; glo = g2; ghi = g1; }
        int p = lo * 8 + hi;
        int slot = atomicAdd(&g_count[p], 1);
        g_tok[p][slot]  = t;
        g_gate[p][slot] = make_float2(glo, ghi);
    }
}

// ---------------- K2: expert compute, register-blocked ----------------
// 256 threads. Phase A: C[64 tok][32 i] = X·D^T, split-K x4 (groups of 64
// threads), per-thread tile 8 tok x 4 i (t = tg+8u, i = ig+8v). Phase B:
// out[64][2048] = A[64][32]·U, per-thread tile 4 tok x 16 h (h scattered
// 4*hg + 64*m so each u-load is one contiguous 256B span).
__global__ __launch_bounds__(256, 1)
void expert_kernel(const float* __restrict__ x,
                   const float* __restrict__ dw,
                   const float* __restrict__ uw,
                   float* __restrict__ out) {
    const int p  = blockIdx.y;
    const int lo = p >> 3, hi = p & 7;
    if (lo >= hi) return;
    const int cnt = g_count[p];
    if (cnt == 0) return;

    extern __shared__ float sm[];
    float* Xs  = sm + XS_OFF;
    float* Ds  = sm + DS_OFF;
    float* Red = sm + RED_OFF;
    float* As  = sm + AS_OFF;
    float* Us  = sm;                       // reuses Xs/Ds region in phase B

    __shared__ int    Ts[TB];
    __shared__ float2 Gs[TB];

    const int tid = threadIdx.x;
    // phase A ids
    const int kg = tid >> 6;               // k-split group 0..3
    const int g  = tid & 63;
    const int tg = g & 7;                  // token interleave 0..7
    const int ig = g >> 3;                 // i interleave 0..7
    // phase B ids
    const int tokg = tid >> 4;             // 0..15 (4 tokens each)
    const int hg   = tid & 15;             // 0..15

    for (int tile = blockIdx.x; tile * TB < cnt; tile += gridDim.x) {
        const int base = tile * TB;
        const int n = min(TB, cnt - base);

        __syncthreads();                   // prev tile done with Ts/Gs/smem
        if (tid < TB) {
            int src = base + ((tid < n) ? tid : 0);
            Ts[tid] = g_tok[p][src];
            float2 gg = g_gate[p][src];
            if (tid >= n) gg = make_float2(0.f, 0.f);
            Gs[tid] = gg;
        }
        __syncthreads();

        // ---------------- Phase A ----------------
        float acc[8][4];
#pragma unroll
        for (int u = 0; u < 8; u++)
#pragma unroll
            for (int v = 0; v < 4; v++) acc[u][v] = 0.f;

        for (int c = 0; c < H / KC; c++) {
            __syncthreads();
            // stage Xs[64][KC]
            for (int idx = tid; idx < 64 * (KC / 4); idx += 256) {
                int r = idx >> 6, q = idx & 63;
                ((float4*)(Xs + r * XP))[q] =
                    ((const float4*)(x + (size_t)Ts[r] * H + c * KC))[q];
            }
            // stage Ds[32][KC]: rows 0..15 expert lo, 16..31 expert hi
            for (int idx = tid; idx < 32 * (KC / 4); idx += 256) {
                int r = idx >> 6, q = idx & 63;
                int e = (r < 16) ? lo : hi;
                ((float4*)(Ds + r * XP))[q] =
                    ((const float4*)(dw + (size_t)(e * I16 + (r & 15)) * H + c * KC))[q];
            }
            __syncthreads();

            const float4* Xb = (const float4*)Xs + tg * (XP / 4) + kg * 16;
            const float4* Db = (const float4*)Ds + ig * (XP / 4) + kg * 16;
#pragma unroll 4
            for (int qq = 0; qq < 16; qq++) {
                float4 xv[8];
#pragma unroll
                for (int u = 0; u < 8; u++) xv[u] = Xb[u * 8 * (XP / 4) + qq];
#pragma unroll
                for (int v = 0; v < 4; v++) {
                    float4 dv = Db[v * 8 * (XP / 4) + qq];
#pragma unroll
                    for (int u = 0; u < 8; u++) {
                        acc[u][v] = fmaf(xv[u].x, dv.x, acc[u][v]);
                        acc[u][v] = fmaf(xv[u].y, dv.y, acc[u][v]);
                        acc[u][v] = fmaf(xv[u].z, dv.z, acc[u][v]);
                        acc[u][v] = fmaf(xv[u].w, dv.w, acc[u][v]);
                    }
                }
            }
        }

        // write split-K partials
#pragma unroll
        for (int u = 0; u < 8; u++)
#pragma unroll
            for (int v = 0; v < 4; v++)
                Red[kg * 2048 + (tg + 8 * u) * 32 + (ig + 8 * v)] = acc[u][v];
        __syncthreads();

        // reduce + silu + gate -> As
#pragma unroll
        for (int j = 0; j < 8; j++) {
            int idx = j * 256 + tid;
            int t = idx >> 5, i = idx & 31;
            float hv = Red[idx] + Red[2048 + idx] + Red[4096 + idx] + Red[6144 + idx];
            float2 gg = Gs[t];
            float gate = (i < 16) ? gg.x : gg.y;
            float sig = 1.f / (1.f + __expf(-hv));
            As[t * ASP + i] = gate * hv * sig;
        }
        __syncthreads();

        // ---------------- Phase B ----------------
        for (int hc = 0; hc < H; hc += 256) {
            __syncthreads();               // Us region free
            // stage Us[32 i][256 h]
            for (int idx = tid; idx < 2048; idx += 256) {
                int e2 = idx >> 10;
                int rm = idx & 1023;
                int h  = rm >> 2;
                int iq = rm & 3;
                int eg = e2 ? hi : lo;
                float4 v = *(const float4*)(uw + ((size_t)eg * H + hc + h) * I16 + 4 * iq);
                int rb = e2 * 16 + 4 * iq;
                Us[(rb + 0) * UP + h] = v.x;
                Us[(rb + 1) * UP + h] = v.y;
                Us[(rb + 2) * UP + h] = v.z;
                Us[(rb + 3) * UP + h] = v.w;
            }
            __syncthreads();

            float4 o[4][4];
#pragma unroll
            for (int j = 0; j < 4; j++)
#pragma unroll
                for (int m = 0; m < 4; m++) o[j][m] = make_float4(0.f, 0.f, 0.f, 0.f);

            const float4* U4 = (const float4*)Us + hg;   // + k*(UP/4) + 16*m
            const float*  Ab = As + (tokg * 4) * ASP;
#pragma unroll 8
            for (int k = 0; k < 32; k++) {
                float a0 = Ab[0 * ASP + k];
                float a1 = Ab[1 * ASP + k];
                float a2 = Ab[2 * ASP + k];
                float a3 = Ab[3 * ASP + k];
#pragma unroll
                for (int m = 0; m < 4; m++) {
                    float4 uv = U4[k * (UP / 4) + m * 16];
                    o[0][m].x = fmaf(a0, uv.x, o[0][m].x);
                    o[0][m].y = fmaf(a0, uv.y, o[0][m].y);
                    o[0][m].z = fmaf(a0, uv.z, o[0][m].z);
                    o[0][m].w = fmaf(a0, uv.w, o[0][m].w);
                    o[1][m].x = fmaf(a1, uv.x, o[1][m].x);
                    o[1][m].y = fmaf(a1, uv.y, o[1][m].y);
                    o[1][m].z = fmaf(a1, uv.z, o[1][m].z);
                    o[1][m].w = fmaf(a1, uv.w, o[1][m].w);
                    o[2][m].x = fmaf(a2, uv.x, o[2][m].x);
                    o[2][m].y = fmaf(a2, uv.y, o[2][m].y);
                    o[2][m].z = fmaf(a2, uv.z, o[2][m].z);
                    o[2][m].w = fmaf(a2, uv.w, o[2][m].w);
                    o[3][m].x = fmaf(a3, uv.x, o[3][m].x);
                    o[3][m].y = fmaf(a3, uv.y, o[3][m].y);
                    o[3][m].z = fmaf(a3, uv.z, o[3][m].z);
                    o[3][m].w = fmaf(a3, uv.w, o[3][m].w);
                }
            }

#pragma unroll
            for (int j = 0; j < 4; j++) {
                int tl = tokg * 4 + j;
                if (tl < n) {
                    float* orow = out + (size_t)Ts[tl] * H + hc + 4 * hg;
#pragma unroll
                    for (int m = 0; m < 4; m++)
                        *(float4*)(orow + m * 64) = o[j][m];
                }
            }
        }
    }
}

// ---------------- launch ----------------
extern "C" void kernel_launch(void* const* d_in, const int* in_sizes, int n_in,
                              void* d_out, int out_size) {
    const float* x  = (const float*)d_in[0];
    const float* rw = (const float*)d_in[1];
    const float* dw = (const float*)d_in[2];
    const float* uw = (const float*)d_in[3];
    float* out = (float*)d_out;

    const int rs_smem = E * H * sizeof(float);             // 64 KB
    const int ek_smem = SM_FLOATS * sizeof(float);         // 141056 B
    cudaFuncSetAttribute(router_kernel, cudaFuncAttributeMaxDynamicSharedMemorySize, rs_smem);
    cudaFuncSetAttribute(expert_kernel, cudaFuncAttributeMaxDynamicSharedMemorySize, ek_smem);

    zero_counts_kernel<<<1, 64>>>();
    router_kernel<<<NTOK / 8, 256, rs_smem>>>(x, rw);
    expert_kernel<<<dim3(8, NB), 256, ek_smem>>>(x, dw, uw, out);
}

// round 4
// speedup vs baseline: 3.8413x; 1.4729x over previous
#include <cuda_runtime.h>
#include <math.h>

// Problem constants
#define H    2048
#define E    8
#define I16  16
#define NTOK 8192          // B*T
#define NB   64            // bucket ids lo*8+hi (28 valid)
#define TB   64            // tokens per tile
#define KC   128           // k-chunk (phase A)
#define NCH  (H / KC)      // 16
#define XP   132           // Xs/Ds row pitch (floats): mod 32 = 4
#define ASP  68            // As/Red pitch over tokens (16B-aligned, mod 32 = 4)
#define UP   260           // Us row pitch (floats)

// smem layout (float offsets). Us (phase B) reuses the Xs/Ds region.
#define XS_OFF  0                        // Xs[64][XP]   = 8448
#define DS_OFF  (64 * XP)                // Ds[32][XP]   = 4224
#define RED_OFF (DS_OFF + 32 * XP)       // Red[4][32*ASP] = 8704
#define AS_OFF  (RED_OFF + 4 * 32 * ASP) // As[32][ASP]  = 2176
#define SM_FLOATS (AS_OFF + 32 * ASP)    // 23552 floats = 94208 B
#define EK_SMEM_REQ (120 * 1024)         // force 1 CTA/SM

// packed f32x2 helpers (PTX-only FFMA2: 2 MACs/instr, 128 MAC/cyc/SM)
#define FMA2(d, a, b) asm("fma.rn.f32x2 %0, %1, %2, %0;" : "+l"(d) : "l"(a), "l"(b))
#define PACK2(d, f)   asm("mov.b64 %0, {%1, %1};" : "=l"(d) : "f"(f))
#define UNPACK2(lo, hi, d) asm("mov.b64 {%0, %1}, %2;" : "=f"(lo), "=f"(hi) : "l"(d))

// ---------------- device scratch ----------------
__device__ int    g_count[NB];
__device__ int    g_tok[NB][NTOK];
__device__ float2 g_gate[NB][NTOK];

// ---------------- K1: router (2 tokens per warp, f32x2) ----------------
__global__ __launch_bounds__(256)
void router_kernel(const float* __restrict__ x,
                   const float* __restrict__ rw) {
    extern __shared__ float Rs[];   // [E][H] = 64 KB
    for (int idx = threadIdx.x; idx < (E * H) / 4; idx += blockDim.x)
        ((float4*)Rs)[idx] = ((const float4*)rw)[idx];
    __syncthreads();

    const int w = threadIdx.x >> 5;
    const int l = threadIdx.x & 31;
    const int t0 = blockIdx.x * 16 + w * 2;

    const ulonglong2* xr0 = (const ulonglong2*)(x + (size_t)t0 * H);
    const ulonglong2* xr1 = xr0 + (H / 4);

    unsigned long long accA[E], accB[E];
#pragma unroll
    for (int e = 0; e < E; e++) { accA[e] = 0ull; accB[e] = 0ull; }

#pragma unroll 4
    for (int s = 0; s < 16; s++) {
        ulonglong2 xa = xr0[l + 32 * s];
        ulonglong2 xb = xr1[l + 32 * s];
#pragma unroll
        for (int e = 0; e < E; e++) {
            ulonglong2 wv = ((const ulonglong2*)(Rs + e * H))[l + 32 * s];
            FMA2(accA[e], xa.x, wv.x);
            FMA2(accA[e], xa.y, wv.y);
            FMA2(accB[e], xb.x, wv.x);
            FMA2(accB[e], xb.y, wv.y);
        }
    }

    float lgA[E], lgB[E];
#pragma unroll
    for (int e = 0; e < E; e++) {
        float a0, a1, b0, b1;
        UNPACK2(a0, a1, accA[e]);
        UNPACK2(b0, b1, accB[e]);
        float va = a0 + a1, vb = b0 + b1;
#pragma unroll
        for (int o = 16; o > 0; o >>= 1) {
            va += __shfl_xor_sync(0xffffffffu, va, o);
            vb += __shfl_xor_sync(0xffffffffu, vb, o);
        }
        lgA[e] = va; lgB[e] = vb;
    }

    if (l < 2) {
        float lg[E];
#pragma unroll
        for (int e = 0; e < E; e++) lg[e] = (l == 0) ? lgA[e] : lgB[e];
        int t = t0 + l;

        float m = lg[0];
#pragma unroll
        for (int e = 1; e < E; e++) m = fmaxf(m, lg[e]);
        float wgt[E]; float ssum = 0.f;
#pragma unroll
        for (int e = 0; e < E; e++) { wgt[e] = __expf(lg[e] - m); ssum += wgt[e]; }
        float inv = 1.f / ssum;

        int i1 = 0; float v1 = wgt[0];
#pragma unroll
        for (int e = 1; e < E; e++) if (wgt[e] > v1) { v1 = wgt[e]; i1 = e; }
        int i2 = -1; float v2 = -1.f;
#pragma unroll
        for (int e = 0; e < E; e++)
            if (e != i1 && wgt[e] > v2) { v2 = wgt[e]; i2 = e; }

        float g1 = v1 * inv, g2 = v2 * inv;
        int lo, hi; float glo, ghi;
        if (i1 < i2) { lo = i1; hi = i2; glo = g1; ghi = g2; }
        else         { lo = i2; hi = i1; glo = g2; ghi = g1; }
        int p = lo * 8 + hi;
        int slot = atomicAdd(&g_count[p], 1);
        g_tok[p][slot]  = t;
        g_gate[p][slot] = make_float2(glo, ghi);
    }
}

// ---------------- K2: expert compute, f32x2 + reg-prefetch pipeline ------
__global__ __launch_bounds__(256, 1)
void expert_kernel(const float* __restrict__ x,
                   const float* __restrict__ dw,
                   const float* __restrict__ uw,
                   float* __restrict__ out) {
    const int p  = blockIdx.y;
    const int lo = p >> 3, hi = p & 7;
    if (lo >= hi) return;
    const int cnt = g_count[p];
    if (cnt == 0) return;

    extern __shared__ float sm[];
    float* Xs  = sm + XS_OFF;
    float* Ds  = sm + DS_OFF;
    float* Red = sm + RED_OFF;
    float* As  = sm + AS_OFF;
    float* Us  = sm;                 // reuses Xs/Ds region in phase B

    __shared__ int    Ts[TB];
    __shared__ float2 Gs[TB];

    const int tid = threadIdx.x;
    // phase A ids
    const int kg = tid >> 6;         // k-split group 0..3
    const int g  = tid & 63;
    const int tg = g & 7;            // token interleave
    const int ig = g >> 3;           // i interleave 0..7
    // phase B ids
    const int tokg = tid >> 4;       // 0..15 (4 tokens each)
    const int hg   = tid & 15;

    for (int tile = blockIdx.x; tile * TB < cnt; tile += gridDim.x) {
        const int base = tile * TB;
        const int n = min(TB, cnt - base);

        __syncthreads();             // prev tile fully done
        if (tid < TB) {
            int src = base + ((tid < n) ? tid : 0);
            Ts[tid] = g_tok[p][src];
            float2 gg = g_gate[p][src];
            if (tid >= n) gg = make_float2(0.f, 0.f);
            Gs[tid] = gg;
        }
        __syncthreads();

        // ================= Phase A =================
        unsigned long long accP[8][4];
#pragma unroll
        for (int u = 0; u < 8; u++)
#pragma unroll
            for (int v = 0; v < 4; v++) accP[u][v] = 0ull;

        // prefetch chunk 0 into registers
        float4 pfx[8], pfd[4];
#pragma unroll
        for (int j = 0; j < 8; j++) {
            int idx = tid + 256 * j, r = idx >> 5, q = idx & 31;
            pfx[j] = *(const float4*)(x + (size_t)Ts[r] * H + 4 * q);
        }
#pragma unroll
        for (int j = 0; j < 4; j++) {
            int idx = tid + 256 * j, r = idx >> 5, q = idx & 31;
            int e = (r < 16) ? lo : hi;
            pfd[j] = *(const float4*)(dw + (size_t)(e * I16 + (r & 15)) * H + 4 * q);
        }

        for (int c = 0; c < NCH; c++) {
            __syncthreads();         // consumers of previous chunk done
            // commit prefetched chunk c to smem
#pragma unroll
            for (int j = 0; j < 8; j++) {
                int idx = tid + 256 * j, r = idx >> 5, q = idx & 31;
                *(float4*)(Xs + r * XP + 4 * q) = pfx[j];
            }
#pragma unroll
            for (int j = 0; j < 4; j++) {
                int idx = tid + 256 * j, r = idx >> 5, q = idx & 31;
                *(float4*)(Ds + r * XP + 4 * q) = pfd[j];
            }
            // issue prefetch for chunk c+1 (completes during compute)
            if (c + 1 < NCH) {
                int off = (c + 1) * KC;
#pragma unroll
                for (int j = 0; j < 8; j++) {
                    int idx = tid + 256 * j, r = idx >> 5, q = idx & 31;
                    pfx[j] = *(const float4*)(x + (size_t)Ts[r] * H + off + 4 * q);
                }
#pragma unroll
                for (int j = 0; j < 4; j++) {
                    int idx = tid + 256 * j, r = idx >> 5, q = idx & 31;
                    int e = (r < 16) ? lo : hi;
                    pfd[j] = *(const float4*)(dw + (size_t)(e * I16 + (r & 15)) * H + off + 4 * q);
                }
            }
            __syncthreads();

            const ulonglong2* Xb = (const ulonglong2*)Xs + tg * (XP / 4) + kg * 8;
            const ulonglong2* Db = (const ulonglong2*)Ds + ig * (XP / 4) + kg * 8;
#pragma unroll
            for (int qq = 0; qq < 8; qq++) {
                ulonglong2 xv[8];
#pragma unroll
                for (int u = 0; u < 8; u++) xv[u] = Xb[u * 8 * (XP / 4) + qq];
#pragma unroll
                for (int v = 0; v < 4; v++) {
                    ulonglong2 dv = Db[v * 8 * (XP / 4) + qq];
#pragma unroll
                    for (int u = 0; u < 8; u++) {
                        FMA2(accP[u][v], xv[u].x, dv.x);
                        FMA2(accP[u][v], xv[u].y, dv.y);
                    }
                }
            }
        }

        // prefetch Us chunk 0 while accs settle (no smem touch)
        float4 pfu[8];
#pragma unroll
        for (int j = 0; j < 8; j++) {
            int idx = tid + 256 * j;
            int e2 = idx >> 10, rm = idx & 1023, h = rm >> 2, iq = rm & 3;
            int eg = e2 ? hi : lo;
            pfu[j] = *(const float4*)(uw + ((size_t)eg * H + h) * I16 + 4 * iq);
        }

        // write split-K partials (transposed [i][t])
#pragma unroll
        for (int u = 0; u < 8; u++)
#pragma unroll
            for (int v = 0; v < 4; v++) {
                float s0, s1;
                UNPACK2(s0, s1, accP[u][v]);
                Red[kg * (32 * ASP) + (ig + 8 * v) * ASP + (tg + 8 * u)] = s0 + s1;
            }
        __syncthreads();

        // reduce + silu + gate -> As[i][t]
#pragma unroll
        for (int j = 0; j < 8; j++) {
            int idx = j * 256 + tid;
            int i = idx >> 6, t = idx & 63;
            int o2 = i * ASP + t;
            float hv = Red[o2] + Red[32 * ASP + o2] + Red[64 * ASP + o2] + Red[96 * ASP + o2];
            float2 gg = Gs[t];
            float gate = (i < 16) ? gg.x : gg.y;
            float sig = 1.f / (1.f + __expf(-hv));
            As[o2] = gate * hv * sig;
        }
        __syncthreads();             // As ready; Xs/Ds region free

        // ================= Phase B =================
        for (int hc = 0; hc < H; hc += 256) {
            // commit prefetched Us chunk (transpose scatter)
#pragma unroll
            for (int j = 0; j < 8; j++) {
                int idx = tid + 256 * j;
                int e2 = idx >> 10, rm = idx & 1023, h = rm >> 2, iq = rm & 3;
                int rb = e2 * 16 + 4 * iq;
                Us[(rb + 0) * UP + h] = pfu[j].x;
                Us[(rb + 1) * UP + h] = pfu[j].y;
                Us[(rb + 2) * UP + h] = pfu[j].z;
                Us[(rb + 3) * UP + h] = pfu[j].w;
            }
            // prefetch next Us chunk
            if (hc + 256 < H) {
#pragma unroll
                for (int j = 0; j < 8; j++) {
                    int idx = tid + 256 * j;
                    int e2 = idx >> 10, rm = idx & 1023, h = rm >> 2, iq = rm & 3;
                    int eg = e2 ? hi : lo;
                    pfu[j] = *(const float4*)(uw + ((size_t)eg * H + hc + 256 + h) * I16 + 4 * iq);
                }
            }
            __syncthreads();

            ulonglong2 oP[4][4];
#pragma unroll
            for (int j = 0; j < 4; j++)
#pragma unroll
                for (int m = 0; m < 4; m++) { oP[j][m].x = 0ull; oP[j][m].y = 0ull; }

            const ulonglong2* U4 = (const ulonglong2*)Us + hg;
#pragma unroll 8
            for (int k = 0; k < 32; k++) {
                float4 a4 = *(const float4*)(As + k * ASP + tokg * 4);
                unsigned long long aP[4];
                PACK2(aP[0], a4.x);
                PACK2(aP[1], a4.y);
                PACK2(aP[2], a4.z);
                PACK2(aP[3], a4.w);
#pragma unroll
                for (int m = 0; m < 4; m++) {
                    ulonglong2 uv = U4[k * (UP / 4) + m * 16];
#pragma unroll
                    for (int j = 0; j < 4; j++) {
                        FMA2(oP[j][m].x, aP[j], uv.x);
                        FMA2(oP[j][m].y, aP[j], uv.y);
                    }
                }
            }

#pragma unroll
            for (int j = 0; j < 4; j++) {
                int tl = tokg * 4 + j;
                if (tl < n) {
                    float* orow = out + (size_t)Ts[tl] * H + hc + 4 * hg;
#pragma unroll
                    for (int m = 0; m < 4; m++) {
                        float4 ov;
                        UNPACK2(ov.x, ov.y, oP[j][m].x);
                        UNPACK2(ov.z, ov.w, oP[j][m].y);
                        *(float4*)(orow + m * 64) = ov;
                    }
                }
            }
            __syncthreads();         // before overwriting Us
        }
    }
}

// ---------------- launch ----------------
extern "C" void kernel_launch(void* const* d_in, const int* in_sizes, int n_in,
                              void* d_out, int out_size) {
    const float* x  = (const float*)d_in[0];
    const float* rw = (const float*)d_in[1];
    const float* dw = (const float*)d_in[2];
    const float* uw = (const float*)d_in[3];
    float* out = (float*)d_out;

    const int rs_smem = E * H * sizeof(float);   // 64 KB
    cudaFuncSetAttribute(router_kernel, cudaFuncAttributeMaxDynamicSharedMemorySize, rs_smem);
    cudaFuncSetAttribute(expert_kernel, cudaFuncAttributeMaxDynamicSharedMemorySize, EK_SMEM_REQ);

    void* cnt_ptr = nullptr;
    cudaGetSymbolAddress(&cnt_ptr, g_count);
    cudaMemsetAsync(cnt_ptr, 0, NB * sizeof(int));

    router_kernel<<<NTOK / 16, 256, rs_smem>>>(x, rw);
    expert_kernel<<<dim3(8, NB), 256, EK_SMEM_REQ>>>(x, dw, uw, out);
}

// round 5
// speedup vs baseline: 3.8883x; 1.0122x over previous
#include <cuda_runtime.h>
#include <math.h>

// Problem constants
#define H    2048
#define E    8
#define I16  16
#define NTOK 8192
#define NB   64            // bucket ids lo*8+hi (28 valid)
#define TB   64            // tokens per tile
#define KC   128           // k-chunk (phase A)
#define NCH  (H / KC)      // 16
#define XP   132           // X/D row pitch (floats), mod 32 = 4
#define ASP  68            // Red/As pitch over tokens
#define UP   516           // Us row pitch (floats)

// smem layout (float offsets)
#define XDSZ     (96 * XP)                 // one X+D buffer: 12672 floats
#define RED_OFF  (2 * XDSZ)                // 25344
#define AS_OFF   (RED_OFF + 8 * 32 * ASP)  // 25344 + 17408 = 42752
#define SM_FLOATS (AS_OFF + 32 * ASP)      // 44928 floats = 179712 B

// f32x2 packed-math helpers
#define FMA2(d, a, b) asm("fma.rn.f32x2 %0, %1, %2, %0;" : "+l"(d) : "l"(a), "l"(b))
#define PACK2(d, f)   asm("mov.b64 %0, {%1, %1};" : "=l"(d) : "f"(f))
#define UNPACK2(lo, hi, d) asm("mov.b64 {%0, %1}, %2;" : "=f"(lo), "=f"(hi) : "l"(d))

__device__ __forceinline__ unsigned su32(const void* p) {
    return (unsigned)__cvta_generic_to_shared(p);
}
#define CP16(dst, src) asm volatile("cp.async.cg.shared.global [%0], [%1], 16;" :: "r"(dst), "l"(src))
#define CP_COMMIT()    asm volatile("cp.async.commit_group;" ::: "memory")
#define CP_WAIT1()     asm volatile("cp.async.wait_group 1;" ::: "memory")
#define CP_WAIT0()     asm volatile("cp.async.wait_group 0;" ::: "memory")

// ---------------- device scratch ----------------
__device__ int    g_count[NB];
__device__ int    g_tok[NB][NTOK];
__device__ float2 g_gate[NB][NTOK];

// ---------------- K1: router (2 tokens per warp, f32x2) ----------------
__global__ __launch_bounds__(256)
void router_kernel(const float* __restrict__ x,
                   const float* __restrict__ rw) {
    extern __shared__ float Rs[];   // [E][H] = 64 KB
    for (int idx = threadIdx.x; idx < (E * H) / 4; idx += blockDim.x)
        ((float4*)Rs)[idx] = ((const float4*)rw)[idx];
    __syncthreads();

    const int w = threadIdx.x >> 5;
    const int l = threadIdx.x & 31;
    const int t0 = blockIdx.x * 16 + w * 2;

    const ulonglong2* xr0 = (const ulonglong2*)(x + (size_t)t0 * H);
    const ulonglong2* xr1 = xr0 + (H / 4);

    unsigned long long accA[E], accB[E];
#pragma unroll
    for (int e = 0; e < E; e++) { accA[e] = 0ull; accB[e] = 0ull; }

#pragma unroll 4
    for (int s = 0; s < 16; s++) {
        ulonglong2 xa = xr0[l + 32 * s];
        ulonglong2 xb = xr1[l + 32 * s];
#pragma unroll
        for (int e = 0; e < E; e++) {
            ulonglong2 wv = ((const ulonglong2*)(Rs + e * H))[l + 32 * s];
            FMA2(accA[e], xa.x, wv.x);
            FMA2(accA[e], xa.y, wv.y);
            FMA2(accB[e], xb.x, wv.x);
            FMA2(accB[e], xb.y, wv.y);
        }
    }

    float lgA[E], lgB[E];
#pragma unroll
    for (int e = 0; e < E; e++) {
        float a0, a1, b0, b1;
        UNPACK2(a0, a1, accA[e]);
        UNPACK2(b0, b1, accB[e]);
        float va = a0 + a1, vb = b0 + b1;
#pragma unroll
        for (int o = 16; o > 0; o >>= 1) {
            va += __shfl_xor_sync(0xffffffffu, va, o);
            vb += __shfl_xor_sync(0xffffffffu, vb, o);
        }
        lgA[e] = va; lgB[e] = vb;
    }

    if (l < 2) {
        float lg[E];
#pragma unroll
        for (int e = 0; e < E; e++) lg[e] = (l == 0) ? lgA[e] : lgB[e];
        int t = t0 + l;

        float m = lg[0];
#pragma unroll
        for (int e = 1; e < E; e++) m = fmaxf(m, lg[e]);
        float wgt[E]; float ssum = 0.f;
#pragma unroll
        for (int e = 0; e < E; e++) { wgt[e] = __expf(lg[e] - m); ssum += wgt[e]; }
        float inv = 1.f / ssum;

        int i1 = 0; float v1 = wgt[0];
#pragma unroll
        for (int e = 1; e < E; e++) if (wgt[e] > v1) { v1 = wgt[e]; i1 = e; }
        int i2 = -1; float v2 = -1.f;
#pragma unroll
        for (int e = 0; e < E; e++)
            if (e != i1 && wgt[e] > v2) { v2 = wgt[e]; i2 = e; }

        float g1 = v1 * inv, g2 = v2 * inv;
        int lo, hi; float glo, ghi;
        if (i1 < i2) { lo = i1; hi = i2; glo = g1; ghi = g2; }
        else         { lo = i2; hi = i1; glo = g2; ghi = g1; }
        int p = lo * 8 + hi;
        int slot = atomicAdd(&g_count[p], 1);
        g_tok[p][slot]  = t;
        g_gate[p][slot] = make_float2(glo, ghi);
    }
}

// ---------------- K2: expert compute ----------------
// Phase A: C[64 tok][32 i] = X·D^T. split-K x8 (warp w = k range w*16..+16 of
//   each 128-chunk). Thread tile 8 tok x 8 i; cp.async double-buffered staging.
// Phase B: out[64][2048] = A·U. Warp = 8 tokens (uniform), thread tile
//   8 tok x 16 h (h = 4*hg + 128*m within a 512-h chunk).
__global__ __launch_bounds__(256, 1)
void expert_kernel(const float* __restrict__ x,
                   const float* __restrict__ dw,
                   const float* __restrict__ uw,
                   float* __restrict__ out) {
    const int p  = blockIdx.y;
    const int lo = p >> 3, hi = p & 7;
    if (lo >= hi) return;
    const int cnt = g_count[p];
    if (cnt == 0) return;

    extern __shared__ float sm[];
    float* Red = sm + RED_OFF;
    float* As  = sm + AS_OFF;
    float* Us  = sm;                 // reuses XD region in phase B

    __shared__ int    Ts[TB];
    __shared__ float2 Gs[TB];

    const int tid = threadIdx.x;
    const int w = tid >> 5;          // warp = k-split group (A) / token group (B)
    const int l = tid & 31;
    // phase A lane ids
    const int tg = l & 7;            // token interleave
    const int ig = l >> 3;           // i interleave 0..3
    // phase B lane ids
    const int hg = l;                // 0..31

    for (int tile = blockIdx.x; tile * TB < cnt; tile += gridDim.x) {
        const int base = tile * TB;
        const int n = min(TB, cnt - base);

        __syncthreads();
        if (tid < TB) {
            int src = base + ((tid < n) ? tid : 0);
            Ts[tid] = g_tok[p][src];
            float2 gg = g_gate[p][src];
            if (tid >= n) gg = make_float2(0.f, 0.f);
            Gs[tid] = gg;
        }
        __syncthreads();

        // ================= Phase A =================
        unsigned long long accP[8][8];
#pragma unroll
        for (int u = 0; u < 8; u++)
#pragma unroll
            for (int v = 0; v < 8; v++) accP[u][v] = 0ull;

        // cp.async staging of chunk c into buffer b
        auto stage = [&](int c, int b) {
            float* dst = sm + b * XDSZ;
            int koff = c * KC;
#pragma unroll
            for (int j = 0; j < 8; j++) {
                int idx = tid + 256 * j, r = idx >> 5, q = idx & 31;
                CP16(su32(dst + r * XP + 4 * q),
                     x + (size_t)Ts[r] * H + koff + 4 * q);
            }
#pragma unroll
            for (int j = 0; j < 4; j++) {
                int idx = tid + 256 * j, r = idx >> 5, q = idx & 31;
                int e = (r < 16) ? lo : hi;
                CP16(su32(dst + (64 + r) * XP + 4 * q),
                     dw + (size_t)(e * I16 + (r & 15)) * H + koff + 4 * q);
            }
        };

        stage(0, 0); CP_COMMIT();
        stage(1, 1); CP_COMMIT();

        for (int c = 0; c < NCH; c++) {
            if (c == NCH - 1) { CP_WAIT0(); } else { CP_WAIT1(); }
            __syncthreads();
            const ulonglong2* B4 = (const ulonglong2*)(sm + (c & 1) * XDSZ);

#pragma unroll
            for (int q2 = 0; q2 < 4; q2++) {
                const int kq = (w << 2) + q2;
                ulonglong2 xv[8];
#pragma unroll
                for (int u = 0; u < 8; u++)
                    xv[u] = B4[(tg + 8 * u) * 33 + kq];
#pragma unroll
                for (int v = 0; v < 8; v++) {
                    ulonglong2 dv = B4[(64 + ig + 4 * v) * 33 + kq];
#pragma unroll
                    for (int u = 0; u < 8; u++) {
                        FMA2(accP[u][v], xv[u].x, dv.x);
                        FMA2(accP[u][v], xv[u].y, dv.y);
                    }
                }
            }
            __syncthreads();
            if (c + 2 < NCH) { stage(c + 2, c & 1); CP_COMMIT(); }
        }

        // split-K partials -> Red[w][i][t]
#pragma unroll
        for (int u = 0; u < 8; u++)
#pragma unroll
            for (int v = 0; v < 8; v++) {
                float s0, s1;
                UNPACK2(s0, s1, accP[u][v]);
                Red[w * (32 * ASP) + (ig + 4 * v) * ASP + (tg + 8 * u)] = s0 + s1;
            }
        __syncthreads();

        // reduce + silu + gate -> As[i][t]
#pragma unroll
        for (int j = 0; j < 8; j++) {
            int idx = j * 256 + tid;
            int i = idx >> 6, t = idx & 63;
            float hv = 0.f;
#pragma unroll
            for (int kk = 0; kk < 8; kk++)
                hv += Red[kk * (32 * ASP) + i * ASP + t];
            float2 gg = Gs[t];
            float gate = (i < 16) ? gg.x : gg.y;
            float sig = 1.f / (1.f + __expf(-hv));
            As[i * ASP + t] = gate * hv * sig;
        }
        __syncthreads();

        // ================= Phase B =================
        for (int hb = 0; hb < 4; hb++) {
            // stage Us[32 i][512 h]: warp-uniform i-row per STS -> conflict-free
            float4 ub[16];
#pragma unroll
            for (int j = 0; j < 16; j++) {
                int idx = j * 256 + tid;
                int eiq = idx >> 9, h = idx & 511;
                int e2 = eiq >> 2, iq = eiq & 3;
                int eg = e2 ? hi : lo;
                ub[j] = *(const float4*)(uw + ((size_t)eg * H + hb * 512 + h) * I16 + 4 * iq);
            }
#pragma unroll
            for (int j = 0; j < 16; j++) {
                int idx = j * 256 + tid;
                int eiq = idx >> 9, h = idx & 511;
                int e2 = eiq >> 2, iq = eiq & 3;
                int rb = e2 * 16 + 4 * iq;
                Us[(rb + 0) * UP + h] = ub[j].x;
                Us[(rb + 1) * UP + h] = ub[j].y;
                Us[(rb + 2) * UP + h] = ub[j].z;
                Us[(rb + 3) * UP + h] = ub[j].w;
            }
            __syncthreads();

            unsigned long long acc[8][8];   // [token j][h-pair]
#pragma unroll
            for (int j = 0; j < 8; j++)
#pragma unroll
                for (int m = 0; m < 8; m++) acc[j][m] = 0ull;

#pragma unroll 4
            for (int k = 0; k < 32; k++) {
                float4 aA = *(const float4*)(As + k * ASP + w * 8);
                float4 aB = *(const float4*)(As + k * ASP + w * 8 + 4);
                unsigned long long ap[8];
                PACK2(ap[0], aA.x); PACK2(ap[1], aA.y);
                PACK2(ap[2], aA.z); PACK2(ap[3], aA.w);
                PACK2(ap[4], aB.x); PACK2(ap[5], aB.y);
                PACK2(ap[6], aB.z); PACK2(ap[7], aB.w);
#pragma unroll
                for (int m = 0; m < 4; m++) {
                    ulonglong2 uv = *(const ulonglong2*)(Us + k * UP + 4 * hg + 128 * m);
#pragma unroll
                    for (int j = 0; j < 8; j++) {
                        FMA2(acc[j][2 * m],     ap[j], uv.x);
                        FMA2(acc[j][2 * m + 1], ap[j], uv.y);
                    }
                }
            }

#pragma unroll
            for (int j = 0; j < 8; j++) {
                int tl = w * 8 + j;
                if (tl < n) {
                    float* orow = out + (size_t)Ts[tl] * H + hb * 512;
#pragma unroll
                    for (int m = 0; m < 4; m++) {
                        float4 ov;
                        UNPACK2(ov.x, ov.y, acc[j][2 * m]);
                        UNPACK2(ov.z, ov.w, acc[j][2 * m + 1]);
                        *(float4*)(orow + 4 * hg + 128 * m) = ov;
                    }
                }
            }
            __syncthreads();       // before next chunk overwrites Us
        }
    }
}

// ---------------- launch ----------------
extern "C" void kernel_launch(void* const* d_in, const int* in_sizes, int n_in,
                              void* d_out, int out_size) {
    const float* x  = (const float*)d_in[0];
    const float* rw = (const float*)d_in[1];
    const float* dw = (const float*)d_in[2];
    const float* uw = (const float*)d_in[3];
    float* out = (float*)d_out;

    const int rs_smem = E * H * sizeof(float);     // 64 KB
    const int ek_smem = SM_FLOATS * sizeof(float); // 179712 B
    cudaFuncSetAttribute(router_kernel, cudaFuncAttributeMaxDynamicSharedMemorySize, rs_smem);
    cudaFuncSetAttribute(expert_kernel, cudaFuncAttributeMaxDynamicSharedMemorySize, ek_smem);

    void* cnt_ptr = nullptr;
    cudaGetSymbolAddress(&cnt_ptr, g_count);
    cudaMemsetAsync(cnt_ptr, 0, NB * sizeof(int));

    router_kernel<<<NTOK / 16, 256, rs_smem>>>(x, rw);
    expert_kernel<<<dim3(8, NB), 256, ek_smem>>>(x, dw, uw, out);
}